// round 7
// baseline (speedup 1.0000x reference)
#include <cuda_runtime.h>
#include <cuda_fp16.h>
#include <cstdint>

// ---------------------------------------------------------------------------
// SKConv2d via mma.sync (fp16 in / fp32 acc):
//   out = im2col(x) @ W_eff + 2*bias
// Kernel 1: build W transposed to [o][k] fp16, k = tap*128 + c.
// Kernel 2: implicit GEMM, BM=128, BN=256, BK=32, 8 warps (2Mx4N),
//           warp tile 64x64 via m16n8k16; A: LDG+cvt+STS, B: cp.async.
// ---------------------------------------------------------------------------

#define HH    56
#define WWd   56
#define Cc    128
#define OO    256
#define KK    1152
#define PLANE 3136
#define NN    100352
#define Tt    6
#define Rr    8
#define RR2   72

#define BM    128
#define BN    256
#define BK    32
#define NCHUNK 36          // 1152/32 ; tap = kt>>2

// W transposed fp16: g_Wh[o*KK + tap*128 + c]
__device__ __align__(16) __half g_Wh[OO * KK];

// ---------------------------------------------------------------------------
__device__ __forceinline__ uint32_t smem_u32(const void* p) {
    uint32_t a;
    asm("{ .reg .u64 t; cvta.to.shared.u64 t, %1; cvt.u32.u64 %0, t; }" : "=r"(a) : "l"(p));
    return a;
}
__device__ __forceinline__ uint32_t swz(uint32_t off) {   // 64B-row swizzle
    return off ^ ((off >> 3) & 0x30);
}
// pack two fp32 -> half2 bits; f0 -> low half (lower address), f1 -> high half
__device__ __forceinline__ uint32_t pack_h2(float f0, float f1) {
    uint32_t r;
    asm("cvt.rn.f16x2.f32 %0, %1, %2;" : "=r"(r) : "f"(f1), "f"(f0));
    return r;
}
#define STS128V(addr, a, b, c, d) \
    asm volatile("st.shared.v4.b32 [%0], {%1,%2,%3,%4};" :: "r"(addr), "r"(a), "r"(b), "r"(c), "r"(d) : "memory")
#define LDSM_X4(r0, r1, r2, r3, addr) \
    asm volatile("ldmatrix.sync.aligned.m8n8.x4.shared.b16 {%0,%1,%2,%3}, [%4];" \
        : "=r"(r0), "=r"(r1), "=r"(r2), "=r"(r3) : "r"(addr))
#define MMA16816(d, a0, a1, a2, a3, b0, b1)                                   \
    asm volatile("mma.sync.aligned.m16n8k16.row.col.f32.f16.f16.f32 "         \
        "{%0,%1,%2,%3}, {%4,%5,%6,%7}, {%8,%9}, {%0,%1,%2,%3};"               \
        : "+f"((d)[0]), "+f"((d)[1]), "+f"((d)[2]), "+f"((d)[3])              \
        : "r"(a0), "r"(a1), "r"(a2), "r"(a3), "r"(b0), "r"(b1))
#define CP_ASYNC16(dst, src) \
    asm volatile("cp.async.cg.shared.global [%0], [%1], 16;" :: "r"(dst), "l"(src) : "memory")
#define CP_COMMIT() asm volatile("cp.async.commit_group;" ::: "memory")
#define CP_WAIT0()  asm volatile("cp.async.wait_group 0;" ::: "memory")

// ---------------------------------------------------------------------------
// Kernel 1: precompute W_eff -> g_Wh[o][tap*128+c] fp16.
// Grid (36, 4): 32-d x 64-o tiles. 256 threads.
// ---------------------------------------------------------------------------
__global__ void precompute_w(const float* __restrict__ S1s,
                             const float* __restrict__ U1s,
                             const float* __restrict__ U2s,
                             const float* __restrict__ S2s) {
    __shared__ float sS1[32][8];
    __shared__ float sU1[8][64];
    __shared__ float sU2[72][32];
    __shared__ float sS2[72][64];

    const int tid = threadIdx.x;
    const int d0 = blockIdx.x * 32;
    const int o0 = blockIdx.y * 64;
    const int dd = tid & 31;
    const int og = (tid >> 5) * 8;

    float acc[8];
#pragma unroll
    for (int j = 0; j < 8; j++) acc[j] = 0.f;

    for (int t = 0; t < Tt; t++) {
        {   int row = tid >> 3, col = tid & 7;
            sS1[row][col] = S1s[(t * KK + d0 + row) * Rr + col]; }
#pragma unroll
        for (int i = 0; i < 2; i++) {
            int idx = tid + i * 256; int r = idx >> 6, o = idx & 63;
            sU1[r][o] = U1s[(t * Rr + r) * OO + o0 + o]; }
#pragma unroll
        for (int i = 0; i < 9; i++) {
            int idx = tid + i * 256; int r2 = idx >> 5, d = idx & 31;
            sU2[r2][d] = U2s[(t * RR2 + r2) * KK + d0 + d]; }
#pragma unroll
        for (int i = 0; i < 18; i++) {
            int idx = tid + i * 256; int r2 = idx >> 6, o = idx & 63;
            sS2[r2][o] = S2s[(t * RR2 + r2) * OO + o0 + o]; }
        __syncthreads();

#pragma unroll
        for (int r = 0; r < Rr; r++) {
            float a = sS1[dd][r];
#pragma unroll
            for (int j = 0; j < 8; j++) acc[j] += a * sU1[r][og + j];
        }
        for (int r2 = 0; r2 < RR2; r2++) {
            float a = sU2[r2][dd];
#pragma unroll
            for (int j = 0; j < 8; j++) acc[j] += a * sS2[r2][og + j];
        }
        __syncthreads();
    }

    const int d   = d0 + dd;
    const int c   = d / 9;
    const int tap = d - 9 * c;
    const int krow = tap * 128 + c;
#pragma unroll
    for (int j = 0; j < 8; j++)
        g_Wh[(o0 + og + j) * KK + krow] = __float2half_rn(acc[j] * (1.0f / 6.0f));
}

// ---------------------------------------------------------------------------
// Kernel 2: mma.sync implicit GEMM conv. Grid 784, block 256.
// ---------------------------------------------------------------------------
__global__ __launch_bounds__(256)
void conv_mma(const float* __restrict__ x,
              const float* __restrict__ bias,
              float* __restrict__ out) {
    // 64B rows, swizzled. A: 128 rows x 32 halves. B: 256 rows x 32 halves.
    __shared__ __align__(16) __half As[2][BM * BK];
    __shared__ __align__(16) __half Bs[2][BN * BK];

    const int tid  = threadIdx.x;
    const int lane = tid & 31;
    const int wid  = tid >> 5;
    const int wm   = wid & 1;      // 2 warps in M
    const int wn   = wid >> 1;     // 4 warps in N (64 cols each)
    const int bm0  = blockIdx.x * BM;

    const uint32_t aBase[2] = { smem_u32(As[0]), smem_u32(As[1]) };
    const uint32_t bBase[2] = { smem_u32(Bs[0]), smem_u32(Bs[1]) };

    // ---- per-thread A-load geometry: pixel = tid&127, channel half = tid>>7 ----
    const int ml  = tid & 127;
    const int chb = (tid >> 7) * 16;
    const int m   = bm0 + ml;
    const int b   = m / PLANE;
    const int rem = m - b * PLANE;
    const int ohp = rem / WWd;
    const int owp = rem - ohp * WWd;
    const float* xb = x + (size_t)b * (Cc * PLANE);

    int  tapOff[9];
    bool tapOk[9];
#pragma unroll
    for (int tap = 0; tap < 9; tap++) {
        const int kh = tap / 3, kw = tap - 3 * kh;
        const int ih = ohp + kh - 1, iw = owp + kw - 1;
        tapOk[tap]  = ((unsigned)ih < HH) && ((unsigned)iw < WWd);
        tapOff[tap] = ih * WWd + iw;
    }

    float acc[4][8][4];
#pragma unroll
    for (int i = 0; i < 4; i++)
#pragma unroll
        for (int j = 0; j < 8; j++)
#pragma unroll
            for (int q = 0; q < 4; q++) acc[i][j][q] = 0.f;

    uint32_t ra[8];      // staged A halves (16 channels = 8 half2)

    auto loadA = [&](int kt) {
        const int tap = kt >> 2;
        const bool ok = tapOk[tap];
        const float* p = xb + tapOff[tap] + (size_t)((kt & 3) * 32 + chb) * PLANE;
#pragma unroll
        for (int q = 0; q < 8; q++) {
            float f0 = 0.f, f1 = 0.f;
            if (ok) { f0 = p[(2 * q) * PLANE]; f1 = p[(2 * q + 1) * PLANE]; }
            ra[q] = pack_h2(f0, f1);
        }
    };
    auto copyB = [&](int kt, int buf) {           // 1024 x 16B via cp.async
        const int k0 = kt * BK;
        const char* wb = reinterpret_cast<const char*>(g_Wh);
#pragma unroll
        for (int i = 0; i < 4; i++) {
            int f = tid + i * 256;
            int n = f >> 2, ck = f & 3;
            const char* src = wb + (size_t)(n * KK + k0 + ck * 8) * 2;
            CP_ASYNC16(bBase[buf] + swz(n * 64 + ck * 16), src);
        }
        CP_COMMIT();
    };
    auto storeA = [&](int buf) {
        const uint32_t a0 = aBase[buf] + swz(ml * 64 + chb * 2);
        STS128V(a0, ra[0], ra[1], ra[2], ra[3]);
        const uint32_t a1 = aBase[buf] + swz(ml * 64 + chb * 2 + 16);
        STS128V(a1, ra[4], ra[5], ra[6], ra[7]);
    };

    loadA(0); copyB(0, 0);
    storeA(0);
    CP_WAIT0();
    __syncthreads();

    int buf = 0;
#pragma unroll 1
    for (int kt = 0; kt < NCHUNK; kt++) {
        if (kt < NCHUNK - 1) { loadA(kt + 1); copyB(kt + 1, buf ^ 1); }

#pragma unroll
        for (int ks = 0; ks < 2; ks++) {
            const int k0 = ks * 16;
            uint32_t af[4][4], bf[8][2];
            // A: 4 m-tiles of 16
#pragma unroll
            for (int i = 0; i < 4; i++) {
                const int mr = wm * 64 + i * 16 + (lane & 15);
                const int kc = k0 + (lane >> 4) * 8;
                LDSM_X4(af[i][0], af[i][1], af[i][2], af[i][3],
                        aBase[buf] + swz(mr * 64 + kc * 2));
            }
            // B: 4 x ldmatrix.x4, each covering two 8-wide n-tiles
#pragma unroll
            for (int jj = 0; jj < 4; jj++) {
                const int nr = wn * 64 + jj * 16 + ((lane >> 4) & 1) * 8 + (lane & 7);
                const int kc = k0 + ((lane >> 3) & 1) * 8;
                LDSM_X4(bf[2 * jj][0], bf[2 * jj][1], bf[2 * jj + 1][0], bf[2 * jj + 1][1],
                        bBase[buf] + swz(nr * 64 + kc * 2));
            }
#pragma unroll
            for (int i = 0; i < 4; i++)
#pragma unroll
                for (int j = 0; j < 8; j++)
                    MMA16816(acc[i][j], af[i][0], af[i][1], af[i][2], af[i][3],
                             bf[j][0], bf[j][1]);
        }

        if (kt < NCHUNK - 1) {
            storeA(buf ^ 1);
            CP_WAIT0();
            __syncthreads();
            buf ^= 1;
        }
    }

    // ---- epilogue: thread lane holds rows (l>>2, l>>2+8), cols 2*(l&3)+{0,1} ----
#pragma unroll
    for (int i = 0; i < 4; i++) {
        const int mg0 = bm0 + wm * 64 + i * 16 + (lane >> 2);
        const int b0e = mg0 / PLANE;
        const int p0e = mg0 - b0e * PLANE;
        const int mg1 = mg0 + 8;
        const int b1e = mg1 / PLANE;
        const int p1e = mg1 - b1e * PLANE;
        float* o0 = out + (size_t)b0e * (OO * PLANE) + p0e;
        float* o1 = out + (size_t)b1e * (OO * PLANE) + p1e;
#pragma unroll
        for (int j = 0; j < 8; j++) {
            const int o = wn * 64 + j * 8 + (lane & 3) * 2;
            const float bv0 = 2.0f * __ldg(bias + o);
            const float bv1 = 2.0f * __ldg(bias + o + 1);
            o0[(size_t)o * PLANE]       = acc[i][j][0] + bv0;
            o0[(size_t)(o + 1) * PLANE] = acc[i][j][1] + bv1;
            o1[(size_t)o * PLANE]       = acc[i][j][2] + bv0;
            o1[(size_t)(o + 1) * PLANE] = acc[i][j][3] + bv1;
        }
    }
}

// ---------------------------------------------------------------------------
extern "C" void kernel_launch(void* const* d_in, const int* in_sizes, int n_in,
                              void* d_out, int out_size) {
    const float* x    = (const float*)d_in[0];
    const float* S1s  = (const float*)d_in[1];
    const float* U1s  = (const float*)d_in[2];
    const float* U2s  = (const float*)d_in[3];
    const float* S2s  = (const float*)d_in[4];
    const float* bias = (const float*)d_in[5];
    float* out = (float*)d_out;

    precompute_w<<<dim3(36, 4), 256>>>(S1s, U1s, U2s, S2s);
    conv_mma<<<784, 256>>>(x, bias, out);
}

// round 8
// speedup vs baseline: 1.1987x; 1.1987x over previous
#include <cuda_runtime.h>
#include <cuda_fp16.h>
#include <cstdint>

// ---------------------------------------------------------------------------
// SKConv2d via mma.sync (fp16 in / fp32 acc):
//   out = im2col(x) @ W_eff + 2*bias
// Kernel 1: build W transposed to [o][k] fp16, k = tap*128 + c.
// Kernel 2: implicit GEMM, BM=128, BN=256, BK=32, 512 threads,
//           16 warps (4Mx4N), warp tile 32x64 via m16n8k16.
//           A: LDG+cvt+STS, B: cp.async. Double-buffered.
// ---------------------------------------------------------------------------

#define HH    56
#define WWd   56
#define Cc    128
#define OO    256
#define KK    1152
#define PLANE 3136
#define NN    100352
#define Tt    6
#define Rr    8
#define RR2   72

#define BM    128
#define BN    256
#define BK    32
#define NCHUNK 36          // 1152/32 ; tap = kt>>2

// W transposed fp16: g_Wh[o*KK + tap*128 + c]
__device__ __align__(16) __half g_Wh[OO * KK];

// ---------------------------------------------------------------------------
__device__ __forceinline__ uint32_t smem_u32(const void* p) {
    uint32_t a;
    asm("{ .reg .u64 t; cvta.to.shared.u64 t, %1; cvt.u32.u64 %0, t; }" : "=r"(a) : "l"(p));
    return a;
}
__device__ __forceinline__ uint32_t swz(uint32_t off) {   // 64B-row swizzle
    return off ^ ((off >> 3) & 0x30);
}
// pack two fp32 -> half2 bits; f0 -> low half (lower address), f1 -> high half
__device__ __forceinline__ uint32_t pack_h2(float f0, float f1) {
    uint32_t r;
    asm("cvt.rn.f16x2.f32 %0, %1, %2;" : "=r"(r) : "f"(f1), "f"(f0));
    return r;
}
#define STS128V(addr, a, b, c, d) \
    asm volatile("st.shared.v4.b32 [%0], {%1,%2,%3,%4};" :: "r"(addr), "r"(a), "r"(b), "r"(c), "r"(d) : "memory")
#define LDSM_X4(r0, r1, r2, r3, addr) \
    asm volatile("ldmatrix.sync.aligned.m8n8.x4.shared.b16 {%0,%1,%2,%3}, [%4];" \
        : "=r"(r0), "=r"(r1), "=r"(r2), "=r"(r3) : "r"(addr))
#define MMA16816(d, a0, a1, a2, a3, b0, b1)                                   \
    asm volatile("mma.sync.aligned.m16n8k16.row.col.f32.f16.f16.f32 "         \
        "{%0,%1,%2,%3}, {%4,%5,%6,%7}, {%8,%9}, {%0,%1,%2,%3};"               \
        : "+f"((d)[0]), "+f"((d)[1]), "+f"((d)[2]), "+f"((d)[3])              \
        : "r"(a0), "r"(a1), "r"(a2), "r"(a3), "r"(b0), "r"(b1))
#define CP_ASYNC16(dst, src) \
    asm volatile("cp.async.cg.shared.global [%0], [%1], 16;" :: "r"(dst), "l"(src) : "memory")
#define CP_COMMIT() asm volatile("cp.async.commit_group;" ::: "memory")
#define CP_WAIT0()  asm volatile("cp.async.wait_group 0;" ::: "memory")

// ---------------------------------------------------------------------------
// Kernel 1: precompute W_eff -> g_Wh[o][tap*128+c] fp16.
// Grid (36, 4): 32-d x 64-o tiles. 256 threads.
// ---------------------------------------------------------------------------
__global__ void precompute_w(const float* __restrict__ S1s,
                             const float* __restrict__ U1s,
                             const float* __restrict__ U2s,
                             const float* __restrict__ S2s) {
    __shared__ float sS1[32][8];
    __shared__ float sU1[8][64];
    __shared__ float sU2[72][32];
    __shared__ float sS2[72][64];

    const int tid = threadIdx.x;
    const int d0 = blockIdx.x * 32;
    const int o0 = blockIdx.y * 64;
    const int dd = tid & 31;
    const int og = (tid >> 5) * 8;

    float acc[8];
#pragma unroll
    for (int j = 0; j < 8; j++) acc[j] = 0.f;

    for (int t = 0; t < Tt; t++) {
        {   int row = tid >> 3, col = tid & 7;
            sS1[row][col] = S1s[(t * KK + d0 + row) * Rr + col]; }
#pragma unroll
        for (int i = 0; i < 2; i++) {
            int idx = tid + i * 256; int r = idx >> 6, o = idx & 63;
            sU1[r][o] = U1s[(t * Rr + r) * OO + o0 + o]; }
#pragma unroll
        for (int i = 0; i < 9; i++) {
            int idx = tid + i * 256; int r2 = idx >> 5, d = idx & 31;
            sU2[r2][d] = U2s[(t * RR2 + r2) * KK + d0 + d]; }
#pragma unroll
        for (int i = 0; i < 18; i++) {
            int idx = tid + i * 256; int r2 = idx >> 6, o = idx & 63;
            sS2[r2][o] = S2s[(t * RR2 + r2) * OO + o0 + o]; }
        __syncthreads();

#pragma unroll
        for (int r = 0; r < Rr; r++) {
            float a = sS1[dd][r];
#pragma unroll
            for (int j = 0; j < 8; j++) acc[j] += a * sU1[r][og + j];
        }
        for (int r2 = 0; r2 < RR2; r2++) {
            float a = sU2[r2][dd];
#pragma unroll
            for (int j = 0; j < 8; j++) acc[j] += a * sS2[r2][og + j];
        }
        __syncthreads();
    }

    const int d   = d0 + dd;
    const int c   = d / 9;
    const int tap = d - 9 * c;
    const int krow = tap * 128 + c;
#pragma unroll
    for (int j = 0; j < 8; j++)
        g_Wh[(o0 + og + j) * KK + krow] = __float2half_rn(acc[j] * (1.0f / 6.0f));
}

// ---------------------------------------------------------------------------
// Kernel 2: mma.sync implicit GEMM conv. Grid 784, block 512.
// ---------------------------------------------------------------------------
__global__ __launch_bounds__(512, 1)
void conv_mma(const float* __restrict__ x,
              const float* __restrict__ bias,
              float* __restrict__ out) {
    // 64B rows, swizzled. A: 128 rows x 32 halves. B: 256 rows x 32 halves.
    __shared__ __align__(16) __half As[2][BM * BK];
    __shared__ __align__(16) __half Bs[2][BN * BK];

    const int tid  = threadIdx.x;
    const int lane = tid & 31;
    const int wid  = tid >> 5;
    const int wm   = wid & 3;      // 4 warps in M (32 rows each)
    const int wn   = wid >> 2;     // 4 warps in N (64 cols each)
    const int bm0  = blockIdx.x * BM;

    const uint32_t aBase[2] = { smem_u32(As[0]), smem_u32(As[1]) };
    const uint32_t bBase[2] = { smem_u32(Bs[0]), smem_u32(Bs[1]) };

    // ---- per-thread A-load geometry: pixel = tid&127, 8 channels = tid>>7 ----
    const int ml  = tid & 127;
    const int chb = (tid >> 7) * 8;           // channel sub-base within chunk
    const int m   = bm0 + ml;
    const int b   = m / PLANE;
    const int rem = m - b * PLANE;
    const int ohp = rem / WWd;
    const int owp = rem - ohp * WWd;
    const float* xb = x + (size_t)b * (Cc * PLANE);

    int  tapOff[9];
    bool tapOk[9];
#pragma unroll
    for (int tap = 0; tap < 9; tap++) {
        const int kh = tap / 3, kw = tap - 3 * kh;
        const int ih = ohp + kh - 1, iw = owp + kw - 1;
        tapOk[tap]  = ((unsigned)ih < HH) && ((unsigned)iw < WWd);
        tapOff[tap] = ih * WWd + iw;
    }

    float acc[2][8][4];
#pragma unroll
    for (int i = 0; i < 2; i++)
#pragma unroll
        for (int j = 0; j < 8; j++)
#pragma unroll
            for (int q = 0; q < 4; q++) acc[i][j][q] = 0.f;

    uint32_t ra[4];      // staged A halves (8 channels = 4 half2)

    auto loadA = [&](int kt) {
        const int tap = kt >> 2;
        const bool ok = tapOk[tap];
        const float* p = xb + tapOff[tap] + (size_t)((kt & 3) * 32 + chb) * PLANE;
#pragma unroll
        for (int q = 0; q < 4; q++) {
            float f0 = 0.f, f1 = 0.f;
            if (ok) { f0 = p[(2 * q) * PLANE]; f1 = p[(2 * q + 1) * PLANE]; }
            ra[q] = pack_h2(f0, f1);
        }
    };
    auto copyB = [&](int kt, int buf) {           // 1024 x 16B via cp.async
        const int k0 = kt * BK;
        const char* wb = reinterpret_cast<const char*>(g_Wh);
#pragma unroll
        for (int i = 0; i < 2; i++) {
            int f = tid + i * 512;
            int n = f >> 2, ck = f & 3;
            const char* src = wb + (size_t)(n * KK + k0 + ck * 8) * 2;
            CP_ASYNC16(bBase[buf] + swz(n * 64 + ck * 16), src);
        }
        CP_COMMIT();
    };
    auto storeA = [&](int buf) {
        const uint32_t a0 = aBase[buf] + swz(ml * 64 + chb * 2);
        STS128V(a0, ra[0], ra[1], ra[2], ra[3]);
    };

    loadA(0); copyB(0, 0);
    storeA(0);
    CP_WAIT0();
    __syncthreads();

    int buf = 0;
#pragma unroll 1
    for (int kt = 0; kt < NCHUNK; kt++) {
        if (kt < NCHUNK - 1) { loadA(kt + 1); copyB(kt + 1, buf ^ 1); }

#pragma unroll
        for (int ks = 0; ks < 2; ks++) {
            const int k0 = ks * 16;
            uint32_t af[2][4], bf[8][2];
            // A: 2 m-tiles of 16
#pragma unroll
            for (int i = 0; i < 2; i++) {
                const int mr = wm * 32 + i * 16 + (lane & 15);
                const int kc = k0 + (lane >> 4) * 8;
                LDSM_X4(af[i][0], af[i][1], af[i][2], af[i][3],
                        aBase[buf] + swz(mr * 64 + kc * 2));
            }
            // B: 4 x ldmatrix.x4, each covering two 8-wide n-tiles
#pragma unroll
            for (int jj = 0; jj < 4; jj++) {
                const int nr = wn * 64 + jj * 16 + ((lane >> 4) & 1) * 8 + (lane & 7);
                const int kc = k0 + ((lane >> 3) & 1) * 8;
                LDSM_X4(bf[2 * jj][0], bf[2 * jj][1], bf[2 * jj + 1][0], bf[2 * jj + 1][1],
                        bBase[buf] + swz(nr * 64 + kc * 2));
            }
#pragma unroll
            for (int i = 0; i < 2; i++)
#pragma unroll
                for (int j = 0; j < 8; j++)
                    MMA16816(acc[i][j], af[i][0], af[i][1], af[i][2], af[i][3],
                             bf[j][0], bf[j][1]);
        }

        if (kt < NCHUNK - 1) {
            storeA(buf ^ 1);
            CP_WAIT0();
            __syncthreads();
            buf ^= 1;
        }
    }

    // ---- epilogue: thread lane holds rows (l>>2, l>>2+8), cols 2*(l&3)+{0,1} ----
#pragma unroll
    for (int i = 0; i < 2; i++) {
        const int mg0 = bm0 + wm * 32 + i * 16 + (lane >> 2);
        const int b0e = mg0 / PLANE;
        const int p0e = mg0 - b0e * PLANE;
        const int mg1 = mg0 + 8;
        const int b1e = mg1 / PLANE;
        const int p1e = mg1 - b1e * PLANE;
        float* o0 = out + (size_t)b0e * (OO * PLANE) + p0e;
        float* o1 = out + (size_t)b1e * (OO * PLANE) + p1e;
#pragma unroll
        for (int j = 0; j < 8; j++) {
            const int o = wn * 64 + j * 8 + (lane & 3) * 2;
            const float bv0 = 2.0f * __ldg(bias + o);
            const float bv1 = 2.0f * __ldg(bias + o + 1);
            o0[(size_t)o * PLANE]       = acc[i][j][0] + bv0;
            o0[(size_t)(o + 1) * PLANE] = acc[i][j][1] + bv1;
            o1[(size_t)o * PLANE]       = acc[i][j][2] + bv0;
            o1[(size_t)(o + 1) * PLANE] = acc[i][j][3] + bv1;
        }
    }
}

// ---------------------------------------------------------------------------
extern "C" void kernel_launch(void* const* d_in, const int* in_sizes, int n_in,
                              void* d_out, int out_size) {
    const float* x    = (const float*)d_in[0];
    const float* S1s  = (const float*)d_in[1];
    const float* U1s  = (const float*)d_in[2];
    const float* U2s  = (const float*)d_in[3];
    const float* S2s  = (const float*)d_in[4];
    const float* bias = (const float*)d_in[5];
    float* out = (float*)d_out;

    precompute_w<<<dim3(36, 4), 256>>>(S1s, U1s, U2s, S2s);
    conv_mma<<<784, 512>>>(x, bias, out);
}

// round 9
// speedup vs baseline: 1.2864x; 1.0731x over previous
#include <cuda_runtime.h>
#include <cuda_fp16.h>
#include <cstdint>

// ---------------------------------------------------------------------------
// SKConv2d via mma.sync (fp16 in / fp32 acc):
//   out = im2col(x) @ W_eff + 2*bias
// Kernel 0: convert+transpose x -> g_Xh[b][pixel][c] fp16.
// Kernel 1: build W transposed to [o][k] fp16, k = tap*128 + c.
// Kernel 2: implicit GEMM, BM=128, BN=256, BK=32, 512 threads,
//           16 warps (4Mx4N), warp tile 32x64 via m16n8k16.
//           A and B both via cp.async, 4-stage pipeline.
// ---------------------------------------------------------------------------

#define HH    56
#define WWd   56
#define Cc    128
#define OO    256
#define KK    1152
#define PLANE 3136
#define NN    100352
#define Tt    6
#define Rr    8
#define RR2   72

#define BM    128
#define BN    256
#define BK    32
#define NCHUNK 36          // 1152/32 ; tap = kt>>2
#define NSTAGE 4

// smem byte layout per stage: A 8KB, B 16KB
#define A_ST(s)  ((s) * 8192)
#define B_ST(s)  (32768 + (s) * 16384)
#define SMEM_BYTES (32768 + NSTAGE * 16384)    // 98304

// W transposed fp16: g_Wh[o*KK + tap*128 + c]
__device__ __align__(16) __half g_Wh[OO * KK];
// x transposed fp16: g_Xh[(b*PLANE + p)*128 + c]
__device__ __align__(16) __half g_Xh[NN * Cc];

// ---------------------------------------------------------------------------
__device__ __forceinline__ uint32_t smem_u32(const void* p) {
    uint32_t a;
    asm("{ .reg .u64 t; cvta.to.shared.u64 t, %1; cvt.u32.u64 %0, t; }" : "=r"(a) : "l"(p));
    return a;
}
__device__ __forceinline__ uint32_t swz(uint32_t off) {   // 64B-row swizzle
    return off ^ ((off >> 3) & 0x30);
}
#define LDSM_X4(r0, r1, r2, r3, addr) \
    asm volatile("ldmatrix.sync.aligned.m8n8.x4.shared.b16 {%0,%1,%2,%3}, [%4];" \
        : "=r"(r0), "=r"(r1), "=r"(r2), "=r"(r3) : "r"(addr))
#define MMA16816(d, a0, a1, a2, a3, b0, b1)                                   \
    asm volatile("mma.sync.aligned.m16n8k16.row.col.f32.f16.f16.f32 "         \
        "{%0,%1,%2,%3}, {%4,%5,%6,%7}, {%8,%9}, {%0,%1,%2,%3};"               \
        : "+f"((d)[0]), "+f"((d)[1]), "+f"((d)[2]), "+f"((d)[3])              \
        : "r"(a0), "r"(a1), "r"(a2), "r"(a3), "r"(b0), "r"(b1))
#define CP_ASYNC16(dst, src) \
    asm volatile("cp.async.cg.shared.global [%0], [%1], 16;" :: "r"(dst), "l"(src) : "memory")
#define CP_ASYNC16Z(dst, src, sz) \
    asm volatile("cp.async.cg.shared.global [%0], [%1], 16, %2;" :: "r"(dst), "l"(src), "r"(sz) : "memory")
#define CP_COMMIT() asm volatile("cp.async.commit_group;" ::: "memory")
#define CP_WAIT2()  asm volatile("cp.async.wait_group 2;" ::: "memory")
#define CP_WAIT0()  asm volatile("cp.async.wait_group 0;" ::: "memory")

// ---------------------------------------------------------------------------
// Kernel 0: x [32,128,3136] fp32 -> g_Xh [32,3136,128] fp16 (tiled transpose).
// Grid (98, 4, 32), block (32, 8).
// ---------------------------------------------------------------------------
__global__ void cvt_x(const float* __restrict__ x) {
    __shared__ float tile[32][33];
    const int b  = blockIdx.z;
    const int p0 = blockIdx.x * 32;
    const int c0 = blockIdx.y * 32;
    const int tx = threadIdx.x, ty = threadIdx.y;
    const float* xb = x + (size_t)b * Cc * PLANE;
#pragma unroll
    for (int i = 0; i < 4; i++)
        tile[ty + 8 * i][tx] = xb[(size_t)(c0 + ty + 8 * i) * PLANE + p0 + tx];
    __syncthreads();
#pragma unroll
    for (int i = 0; i < 4; i++)
        g_Xh[(size_t)(b * PLANE + p0 + ty + 8 * i) * Cc + c0 + tx] =
            __float2half_rn(tile[tx][ty + 8 * i]);
}

// ---------------------------------------------------------------------------
// Kernel 1: precompute W_eff -> g_Wh[o][tap*128+c] fp16.
// Grid (36, 4): 32-d x 64-o tiles. 256 threads.
// ---------------------------------------------------------------------------
__global__ void precompute_w(const float* __restrict__ S1s,
                             const float* __restrict__ U1s,
                             const float* __restrict__ U2s,
                             const float* __restrict__ S2s) {
    __shared__ float sS1[32][8];
    __shared__ float sU1[8][64];
    __shared__ float sU2[72][32];
    __shared__ float sS2[72][64];

    const int tid = threadIdx.x;
    const int d0 = blockIdx.x * 32;
    const int o0 = blockIdx.y * 64;
    const int dd = tid & 31;
    const int og = (tid >> 5) * 8;

    float acc[8];
#pragma unroll
    for (int j = 0; j < 8; j++) acc[j] = 0.f;

    for (int t = 0; t < Tt; t++) {
        {   int row = tid >> 3, col = tid & 7;
            sS1[row][col] = S1s[(t * KK + d0 + row) * Rr + col]; }
#pragma unroll
        for (int i = 0; i < 2; i++) {
            int idx = tid + i * 256; int r = idx >> 6, o = idx & 63;
            sU1[r][o] = U1s[(t * Rr + r) * OO + o0 + o]; }
#pragma unroll
        for (int i = 0; i < 9; i++) {
            int idx = tid + i * 256; int r2 = idx >> 5, d = idx & 31;
            sU2[r2][d] = U2s[(t * RR2 + r2) * KK + d0 + d]; }
#pragma unroll
        for (int i = 0; i < 18; i++) {
            int idx = tid + i * 256; int r2 = idx >> 6, o = idx & 63;
            sS2[r2][o] = S2s[(t * RR2 + r2) * OO + o0 + o]; }
        __syncthreads();

#pragma unroll
        for (int r = 0; r < Rr; r++) {
            float a = sS1[dd][r];
#pragma unroll
            for (int j = 0; j < 8; j++) acc[j] += a * sU1[r][og + j];
        }
        for (int r2 = 0; r2 < RR2; r2++) {
            float a = sU2[r2][dd];
#pragma unroll
            for (int j = 0; j < 8; j++) acc[j] += a * sS2[r2][og + j];
        }
        __syncthreads();
    }

    const int d   = d0 + dd;
    const int c   = d / 9;
    const int tap = d - 9 * c;
    const int krow = tap * 128 + c;
#pragma unroll
    for (int j = 0; j < 8; j++)
        g_Wh[(o0 + og + j) * KK + krow] = __float2half_rn(acc[j] * (1.0f / 6.0f));
}

// ---------------------------------------------------------------------------
// Kernel 2: mma.sync implicit GEMM conv. Grid 784, block 512, 96KB dyn smem.
// ---------------------------------------------------------------------------
__global__ __launch_bounds__(512, 1)
void conv_mma(const float* __restrict__ bias,
              float* __restrict__ out) {
    extern __shared__ __align__(16) char smem[];
    const uint32_t sb = smem_u32(smem);

    const int tid  = threadIdx.x;
    const int lane = tid & 31;
    const int wid  = tid >> 5;
    const int wm   = wid & 3;      // 4 warps in M (32 rows each)
    const int wn   = wid >> 2;     // 4 warps in N (64 cols each)
    const int bm0  = blockIdx.x * BM;

    // ---- A-copy geometry: this thread fills row ar = tid>>2, 16B seg = tid&3 ----
    const int ar   = tid >> 2;
    const int aseg = tid & 3;
    const int am   = bm0 + ar;
    const int ab   = am / PLANE;
    const int arem = am - ab * PLANE;
    const int aoh  = arem / WWd;
    const int aow  = arem - aoh * WWd;

    const char* xrow[9];     // src base (row start + seg) per tap
    uint32_t    xsz[9];      // 16 if valid else 0
#pragma unroll
    for (int tap = 0; tap < 9; tap++) {
        const int kh = tap / 3, kw = tap - 3 * kh;
        const int ih = aoh + kh - 1, iw = aow + kw - 1;
        const bool ok = ((unsigned)ih < HH) && ((unsigned)iw < WWd);
        const int  off = ok ? (ih * WWd + iw) : 0;
        xrow[tap] = reinterpret_cast<const char*>(
                        g_Xh + (size_t)(ab * PLANE + off) * Cc) + aseg * 16;
        xsz[tap]  = ok ? 16u : 0u;
    }
    // B-copy geometry: 1024 x 16B, this thread does f = tid, tid+512
    const char* wb = reinterpret_cast<const char*>(g_Wh);

    auto issueChunk = [&](int kt) {
        const int s = kt & (NSTAGE - 1);
        const int tap = kt >> 2;
        const int c0  = (kt & 3) * 32;
        // A: 512 x 16B
        CP_ASYNC16Z(sb + A_ST(s) + swz(ar * 64 + aseg * 16),
                    xrow[tap] + c0 * 2, xsz[tap]);
        // B: 1024 x 16B
        const int k0 = kt * BK;
#pragma unroll
        for (int i = 0; i < 2; i++) {
            int f = tid + i * 512;
            int n = f >> 2, ck = f & 3;
            CP_ASYNC16(sb + B_ST(s) + swz(n * 64 + ck * 16),
                       wb + (size_t)(n * KK + k0 + ck * 8) * 2);
        }
        CP_COMMIT();
    };

    float acc[2][8][4];
#pragma unroll
    for (int i = 0; i < 2; i++)
#pragma unroll
        for (int j = 0; j < 8; j++)
#pragma unroll
            for (int q = 0; q < 4; q++) acc[i][j][q] = 0.f;

    issueChunk(0); issueChunk(1); issueChunk(2);

#pragma unroll 1
    for (int kt = 0; kt < NCHUNK; kt++) {
        CP_WAIT2();
        __syncthreads();           // chunk kt visible; stage (kt+3)%4 free
        if (kt + 3 < NCHUNK) issueChunk(kt + 3);

        const int s = kt & (NSTAGE - 1);
        const uint32_t aB = sb + A_ST(s);
        const uint32_t bB = sb + B_ST(s);
#pragma unroll
        for (int ks = 0; ks < 2; ks++) {
            const int k0 = ks * 16;
            uint32_t af[2][4], bf[8][2];
#pragma unroll
            for (int i = 0; i < 2; i++) {
                const int mr = wm * 32 + i * 16 + (lane & 15);
                const int kc = k0 + (lane >> 4) * 8;
                LDSM_X4(af[i][0], af[i][1], af[i][2], af[i][3],
                        aB + swz(mr * 64 + kc * 2));
            }
#pragma unroll
            for (int jj = 0; jj < 4; jj++) {
                const int nr = wn * 64 + jj * 16 + ((lane >> 4) & 1) * 8 + (lane & 7);
                const int kc = k0 + ((lane >> 3) & 1) * 8;
                LDSM_X4(bf[2 * jj][0], bf[2 * jj][1], bf[2 * jj + 1][0], bf[2 * jj + 1][1],
                        bB + swz(nr * 64 + kc * 2));
            }
#pragma unroll
            for (int i = 0; i < 2; i++)
#pragma unroll
                for (int j = 0; j < 8; j++)
                    MMA16816(acc[i][j], af[i][0], af[i][1], af[i][2], af[i][3],
                             bf[j][0], bf[j][1]);
        }
        __syncthreads();           // done reading stage s before it is refilled
    }
    CP_WAIT0();

    // ---- epilogue: thread lane holds rows (l>>2, l>>2+8), cols 2*(l&3)+{0,1} ----
#pragma unroll
    for (int i = 0; i < 2; i++) {
        const int mg0 = bm0 + wm * 32 + i * 16 + (lane >> 2);
        const int b0e = mg0 / PLANE;
        const int p0e = mg0 - b0e * PLANE;
        const int mg1 = mg0 + 8;
        const int b1e = mg1 / PLANE;
        const int p1e = mg1 - b1e * PLANE;
        float* o0 = out + (size_t)b0e * (OO * PLANE) + p0e;
        float* o1 = out + (size_t)b1e * (OO * PLANE) + p1e;
#pragma unroll
        for (int j = 0; j < 8; j++) {
            const int o = wn * 64 + j * 8 + (lane & 3) * 2;
            const float bv0 = 2.0f * __ldg(bias + o);
            const float bv1 = 2.0f * __ldg(bias + o + 1);
            o0[(size_t)o * PLANE]       = acc[i][j][0] + bv0;
            o0[(size_t)(o + 1) * PLANE] = acc[i][j][1] + bv1;
            o1[(size_t)o * PLANE]       = acc[i][j][2] + bv0;
            o1[(size_t)(o + 1) * PLANE] = acc[i][j][3] + bv1;
        }
    }
}

// ---------------------------------------------------------------------------
extern "C" void kernel_launch(void* const* d_in, const int* in_sizes, int n_in,
                              void* d_out, int out_size) {
    const float* x    = (const float*)d_in[0];
    const float* S1s  = (const float*)d_in[1];
    const float* U1s  = (const float*)d_in[2];
    const float* U2s  = (const float*)d_in[3];
    const float* S2s  = (const float*)d_in[4];
    const float* bias = (const float*)d_in[5];
    float* out = (float*)d_out;

    cudaFuncSetAttribute(conv_mma, cudaFuncAttributeMaxDynamicSharedMemorySize,
                         SMEM_BYTES);

    cvt_x<<<dim3(98, 4, 32), dim3(32, 8)>>>(x);
    precompute_w<<<dim3(36, 4), 256>>>(S1s, U1s, U2s, S2s);
    conv_mma<<<784, 512, SMEM_BYTES>>>(bias, out);
}